// round 16
// baseline (speedup 1.0000x reference)
#include <cuda_runtime.h>
#include <cuda_fp16.h>
#include <cstdint>

#define D_MODEL 2048
#define BB 2
#define SS 2048
#define HH 16
#define DHD 128
#define PAST 2048
#define TOTAL 4096
#define BHH 32
#define M_ROWS 4096
// 1/sqrt(128) * log2(e): scores land in log2 domain -> softmax via EX2 only
#define QK_SCALE_L2E ((float)(0.08838834764831845 * 1.4426950408889634))

// Scratch (allocation-free rule). All hold packed fp16 (2 per uint32).
__device__ uint32_t g_Xh[(size_t)M_ROWS * D_MODEL / 2];
__device__ uint32_t g_Wh[4 * (size_t)D_MODEL * D_MODEL / 2];
__device__ uint32_t g_Qh[(size_t)BHH * SS * DHD / 2];    // PERMUTED fragment layout, pre-scaled
__device__ uint32_t g_Kh[(size_t)BHH * TOTAL * DHD / 2]; // plain (bh,key,dh)
__device__ uint32_t g_Vh[(size_t)BHH * DHD * TOTAL / 2]; // V transposed (bh,dh,key), plain
__device__ uint32_t g_Vtmp[(size_t)BHH * SS * DHD / 2];  // new-V plain (bh,s,dh) staging
__device__ uint32_t g_Ah[(size_t)BB * SS * D_MODEL / 2]; // attn (b,s,dm), plain

// ---------------------------------------------------------------------------
// Helpers
// ---------------------------------------------------------------------------
__device__ __forceinline__ uint32_t pack_half2(float lo, float hi) {
    uint32_t r;
    asm("cvt.rn.f16x2.f32 %0, %1, %2;" : "=r"(r) : "f"(hi), "f"(lo));
    return r;
}

__device__ __forceinline__ void mma_f16(float* c,
                                        uint32_t a0, uint32_t a1, uint32_t a2, uint32_t a3,
                                        uint32_t b0, uint32_t b1) {
    asm volatile(
        "mma.sync.aligned.m16n8k16.row.col.f32.f16.f16.f32 "
        "{%0,%1,%2,%3}, {%4,%5,%6,%7}, {%8,%9}, {%0,%1,%2,%3};"
        : "+f"(c[0]), "+f"(c[1]), "+f"(c[2]), "+f"(c[3])
        : "r"(a0), "r"(a1), "r"(a2), "r"(a3), "r"(b0), "r"(b1));
}

__device__ __forceinline__ void ldsm4(uint32_t& r0, uint32_t& r1, uint32_t& r2, uint32_t& r3,
                                      uint32_t saddr) {
    asm volatile("ldmatrix.sync.aligned.m8n8.x4.shared.b16 {%0,%1,%2,%3}, [%4];"
                 : "=r"(r0), "=r"(r1), "=r"(r2), "=r"(r3) : "r"(saddr));
}
__device__ __forceinline__ void ldsm2(uint32_t& r0, uint32_t& r1, uint32_t saddr) {
    asm volatile("ldmatrix.sync.aligned.m8n8.x2.shared.b16 {%0,%1}, [%2];"
                 : "=r"(r0), "=r"(r1) : "r"(saddr));
}

// exp2 on MUFU: 1 issue slot. ex2(0) == 1.0f exactly.
__device__ __forceinline__ float ex2(float x) {
    float r;
    asm("ex2.approx.ftz.f32 %0, %1;" : "=f"(r) : "f"(x));
    return r;
}

__device__ __forceinline__ void cpasync16(void* smem_dst, const void* gsrc) {
    uint32_t s = (uint32_t)__cvta_generic_to_shared(smem_dst);
    asm volatile("cp.async.cg.shared.global [%0], [%1], 16;" :: "r"(s), "l"(gsrc));
}
__device__ __forceinline__ void cpasync_commit() {
    asm volatile("cp.async.commit_group;");
}
__device__ __forceinline__ void cpasync_wait0() {
    asm volatile("cp.async.wait_group 0;");
}
__device__ __forceinline__ void cpasync_wait1() {
    asm volatile("cp.async.wait_group 1;");
}

// ---------------------------------------------------------------------------
// Prep kernels. cvt_all merges x + 4 W converts into ONE launch so that the
// FA kernel sits at launch index 5 (ncu captures -s 5 -c 1 -> FA profile).
// ---------------------------------------------------------------------------
__global__ void cvt_all_kernel(const float4* __restrict__ x,
                               const float4* __restrict__ w0, const float4* __restrict__ w1,
                               const float4* __restrict__ w2, const float4* __restrict__ w3,
                               uint2* __restrict__ xh, uint2* __restrict__ wh) {
    int z = blockIdx.y;
    const int n4w = D_MODEL * D_MODEL / 4;   // 1M float4 per W
    const int n4x = M_ROWS * D_MODEL / 4;    // 2M float4 for x
    int i = blockIdx.x * blockDim.x + threadIdx.x;
    if (z < 4) {
        if (i >= n4w) return;
        const float4* src = (z == 0) ? w0 : (z == 1) ? w1 : (z == 2) ? w2 : w3;
        float4 v = src[i];
        wh[(size_t)z * n4w + i] = make_uint2(pack_half2(v.x, v.y), pack_half2(v.z, v.w));
    } else {
        if (i >= n4x) return;
        float4 v = x[i];
        xh[i] = make_uint2(pack_half2(v.x, v.y), pack_half2(v.z, v.w));
    }
}

__global__ void copy_past_k_kernel(const float4* __restrict__ pk,
                                   float4* __restrict__ kc, uint2* __restrict__ kh) {
    int i = blockIdx.x * blockDim.x + threadIdx.x;
    if (i >= BHH * PAST * DHD / 4) return;
    int bh  = i >> 16;
    int rem = i & 65535;
    int dst = (bh << 17) + rem;
    float4 v = pk[i];
    kc[dst] = v;
    kh[dst] = make_uint2(pack_half2(v.x, v.y), pack_half2(v.z, v.w));
}

__global__ __launch_bounds__(256) void transpose_past_v_kernel(
    const float* __restrict__ pv, float* __restrict__ vc, uint32_t* __restrict__ vt) {
    __shared__ float ts[32][33];
    int bh = blockIdx.z;
    int k0 = blockIdx.x * 32;
    int d0 = blockIdx.y * 32;
    int tx = threadIdx.x & 31, ty = threadIdx.x >> 5;

    const float* src = pv + ((size_t)bh * PAST + k0) * DHD + d0;
    float* cdst      = vc + ((size_t)bh * TOTAL + k0) * DHD + d0;
#pragma unroll
    for (int j = 0; j < 4; j++) {
        int r = ty + 8 * j;
        float v = src[(size_t)r * DHD + tx];
        cdst[(size_t)r * DHD + tx] = v;
        ts[r][tx] = v;   // ts[key][d]
    }
    __syncthreads();
    uint32_t* td = vt + (size_t)bh * DHD * (TOTAL / 2);
    if (tx < 16) {
#pragma unroll
        for (int j = 0; j < 4; j++) {
            int dd = ty + 8 * j;
            td[(size_t)(d0 + dd) * (TOTAL / 2) + (k0 >> 1) + tx] =
                pack_half2(ts[2 * tx][dd], ts[2 * tx + 1][dd]);
        }
    }
}

// Transpose the NEW V rows (fp16 staging -> (bh, d, key) fp16-pair layout).
__global__ __launch_bounds__(256) void transpose_v_new_kernel(
    const uint32_t* __restrict__ vtmp, uint32_t* __restrict__ vt) {
    __shared__ unsigned short ts[32][34];
    int bh = blockIdx.z;
    int k0 = blockIdx.x * 32;
    int d0 = blockIdx.y * 32;
    int t  = threadIdx.x;
    {
        int r = t >> 3, cb = t & 7;
#pragma unroll
        for (int i = 0; i < 2; i++) {
            int c = cb + 8 * i;
            uint32_t v = vtmp[((size_t)bh * SS + k0 + r) * 64 + (d0 >> 1) + c];
            ts[r][2 * c]     = (unsigned short)(v & 0xffffu);
            ts[r][2 * c + 1] = (unsigned short)(v >> 16);
        }
    }
    __syncthreads();
    {
        int dd = t >> 3, kb = t & 7;
        uint32_t* td = vt + (size_t)bh * DHD * (TOTAL / 2);
#pragma unroll
        for (int i = 0; i < 2; i++) {
            int kp = kb + 8 * i;
            uint32_t lo = ts[2 * kp][dd];
            uint32_t hi = ts[2 * kp + 1][dd];
            td[(size_t)(d0 + dd) * (TOTAL / 2) + ((PAST + k0) >> 1) + kp] = lo | (hi << 16);
        }
    }
}

// ---------------------------------------------------------------------------
// FP16 GEMM (round-14 proven): CTA 256x128, 512 threads, 16 warps (4m x 4n),
// warp tile 64x32, BK=32, 3-stage cp.async, ldmatrix fragments.
// ---------------------------------------------------------------------------
#define GBM 256
#define GBN 128
#define LDWA 20
#define GSTG ((GBM + GBN) * LDWA)
#define GEMM_SMEM (3 * GSTG * 4)

template <int FUSED>
__global__ __launch_bounds__(512) void gemm_f16_kernel(
    const uint32_t* __restrict__ A, const uint32_t* __restrict__ Wt,
    float* __restrict__ C0, float* __restrict__ C1, float* __restrict__ C2,
    uint32_t* __restrict__ Qh, uint32_t* __restrict__ Kh, uint32_t* __restrict__ Vt) {
    extern __shared__ uint32_t smg[];
    const int PITCH = D_MODEL / 2;

    int t    = threadIdx.x;
    int warp = t >> 5, lane = t & 31;
    int gid  = lane >> 2, tid4 = lane & 3;
    int wm   = (warp & 3) * 64;
    int wn   = (warp >> 2) * 32;
    int m0   = blockIdx.y * GBM;
    int n0   = blockIdx.x * GBN;
    int z    = FUSED ? blockIdx.z : 0;

    const uint32_t* Ab = A + (size_t)m0 * PITCH;
    const uint32_t* Bb = Wt + (FUSED ? (size_t)z * D_MODEL * PITCH : 0) + (size_t)n0 * PITCH;

    float acc[4][4][4];
#pragma unroll
    for (int mf = 0; mf < 4; mf++)
#pragma unroll
        for (int nf = 0; nf < 4; nf++)
#pragma unroll
            for (int c = 0; c < 4; c++) acc[mf][nf][c] = 0.0f;

    uint32_t smem_b = (uint32_t)__cvta_generic_to_shared(smg);
    uint32_t aoff = ((wm + (lane & 15)) * LDWA + (lane >> 4) * 4) * 4;
    uint32_t boff = (GBM * LDWA + (wn + (lane & 7)) * LDWA + ((lane >> 3) & 1) * 4) * 4;

    const int NT = D_MODEL / 32;

#define GISSUE(KT, STG)                                                         \
    {                                                                           \
        uint32_t* As_ = smg + (STG) * GSTG;                                     \
        uint32_t* Bs_ = As_ + GBM * LDWA;                                       \
        const uint32_t* ab = Ab + (KT) * 16;                                    \
        const uint32_t* bb = Bb + (KT) * 16;                                    \
        _Pragma("unroll")                                                       \
        for (int j = 0; j < 2; j++) {                                           \
            int g = t + 512 * j;                                                \
            int r = g >> 2, c = g & 3;                                          \
            cpasync16(As_ + r * LDWA + c * 4, ab + (size_t)r * PITCH + c * 4);  \
        }                                                                       \
        {                                                                       \
            int r = t >> 2, c = t & 3;                                          \
            cpasync16(Bs_ + r * LDWA + c * 4, bb + (size_t)r * PITCH + c * 4);  \
        }                                                                       \
    }

    GISSUE(0, 0); cpasync_commit();
    GISSUE(1, 1); cpasync_commit();

    for (int kt = 0; kt < NT; kt++) {
        cpasync_wait1();
        __syncthreads();
        if (kt + 2 < NT) GISSUE(kt + 2, (kt + 2) % 3);
        cpasync_commit();

        uint32_t sb = smem_b + (kt % 3) * (GSTG * 4);
        uint32_t bf[4][4];
#pragma unroll
        for (int nf = 0; nf < 4; nf++) {
            ldsm2(bf[nf][0], bf[nf][1], sb + boff + nf * (8 * LDWA * 4));
            ldsm2(bf[nf][2], bf[nf][3], sb + boff + nf * (8 * LDWA * 4) + 32);
        }
#pragma unroll
        for (int mf = 0; mf < 4; mf++) {
            uint32_t x0, x1, x2, x3, y0, y1, y2, y3;
            ldsm4(x0, x1, x2, x3, sb + aoff + mf * (16 * LDWA * 4));
            ldsm4(y0, y1, y2, y3, sb + aoff + mf * (16 * LDWA * 4) + 32);
#pragma unroll
            for (int nf = 0; nf < 4; nf++) {
                mma_f16(acc[mf][nf], x0, x1, x2, x3, bf[nf][0], bf[nf][1]);
                mma_f16(acc[mf][nf], y0, y1, y2, y3, bf[nf][2], bf[nf][3]);
            }
        }
    }
#undef GISSUE

    // Epilogue
    if (FUSED && z == 0) {
        int nbase = n0 + wn;
        int hd  = nbase >> 7;
        int blk = (nbase & 127) >> 5;
#pragma unroll
        for (int mf = 0; mf < 4; mf++)
#pragma unroll
            for (int h = 0; h < 2; h++) {
                int m = m0 + wm + 16 * mf + gid + 8 * h;
                int bb = m >> 11, ss = m & 2047;
                int bhh = bb * HH + hd;
                uint4 u;
                u.x = pack_half2(acc[mf][0][2 * h] * QK_SCALE_L2E, acc[mf][0][2 * h + 1] * QK_SCALE_L2E);
                u.y = pack_half2(acc[mf][1][2 * h] * QK_SCALE_L2E, acc[mf][1][2 * h + 1] * QK_SCALE_L2E);
                u.z = pack_half2(acc[mf][2][2 * h] * QK_SCALE_L2E, acc[mf][2][2 * h + 1] * QK_SCALE_L2E);
                u.w = pack_half2(acc[mf][3][2 * h] * QK_SCALE_L2E, acc[mf][3][2 * h + 1] * QK_SCALE_L2E);
                *(uint4*)&Qh[((size_t)bhh * SS + ss) * 64 + blk * 16 + 4 * tid4] = u;
            }
    } else {
#pragma unroll
        for (int mf = 0; mf < 4; mf++)
#pragma unroll
            for (int nf = 0; nf < 4; nf++)
#pragma unroll
                for (int h = 0; h < 2; h++) {
                    int m = m0 + wm + 16 * mf + gid + 8 * h;
                    int n = n0 + wn + 8 * nf + 2 * tid4;
                    float vx = acc[mf][nf][2 * h];
                    float vy = acc[mf][nf][2 * h + 1];
                    if (!FUSED) {
                        *(float2*)&C0[(size_t)m * D_MODEL + n] = make_float2(vx, vy);
                    } else {
                        int bb = m >> 11, ss = m & 2047;
                        int hd = n >> 7,  di = n & 127;
                        int bhh = bb * HH + hd;
                        if (z == 1) {
                            size_t rowk = (size_t)bhh * TOTAL + (PAST + ss);
                            *(float2*)&C1[rowk * DHD + di] = make_float2(vx, vy);
                            Kh[rowk * 64 + (di >> 1)] = pack_half2(vx, vy);
                        } else {
                            size_t rowk = (size_t)bhh * TOTAL + (PAST + ss);
                            *(float2*)&C2[rowk * DHD + di] = make_float2(vx, vy);
                            Vt[((size_t)bhh * SS + ss) * 64 + (di >> 1)] = pack_half2(vx, vy);
                        }
                    }
                }
    }
}

// ---------------------------------------------------------------------------
// Flash attention, fp16 m16n8k16 mma. Round-14 structure + "ones-column"
// trick: the row sum l is accumulated by 4 extra mma/tile against an all-ones
// B fragment, living in fp32 accumulator la[] that is rescaled with po ->
// removes the per-tile fp32 sum loop + shuffles. l recovered in the epilogue
// by a quad-broadcast from the col-0 lanes.
// ---------------------------------------------------------------------------
#define FBM 64
#define KLD2 68
#define VLD2 36
#define FA_SMEM ((2 * 64 * KLD2 + 2 * 128 * VLD2) * 4)   // 71680 B

__global__ __launch_bounds__(128, 2) void flash_attn_f16_kernel(
    const uint32_t* __restrict__ Qh, const uint32_t* __restrict__ Khg,
    const uint32_t* __restrict__ Vhg, uint32_t* __restrict__ Out) {
    extern __shared__ uint32_t sm[];
    uint32_t* Ks  = sm;                   // [2][64][KLD2]
    uint32_t* Vts = sm + 2 * 64 * KLD2;   // [2][128][VLD2]

    int t    = threadIdx.x;
    int warp = t >> 5, lane = t & 31;
    int gid  = lane >> 2, tid4 = lane & 3;
    int mq   = warp * 16;

    int bh = blockIdx.y;
    int q0 = (gridDim.x - 1 - blockIdx.x) * FBM;

    const uint32_t* Kb = Khg + (size_t)bh * TOTAL * 64;
    const uint32_t* Vb = Vhg + (size_t)bh * DHD * (TOTAL / 2);

    uint4 qA[4], qB[4];
    {
        const uint32_t* Qr0 = Qh + ((size_t)bh * SS + (q0 + mq + gid)) * 64 + 4 * tid4;
        const uint32_t* Qr1 = Qr0 + 8 * 64;
#pragma unroll
        for (int blk = 0; blk < 4; blk++) {
            qA[blk] = *(const uint4*)&Qr0[blk * 16];
            qB[blk] = *(const uint4*)&Qr1[blk * 16];
        }
    }

    uint32_t smem_b = (uint32_t)__cvta_generic_to_shared(sm);
    uint32_t koff = ((lane & 7) * KLD2 + (lane >> 3) * 4) * 4;
    uint32_t voff = (2 * 64 * KLD2) * 4 + ((lane & 7) * VLD2 + (lane >> 3) * 4) * 4;

    const uint32_t ONE2 = 0x3C003C00u;   // half2(1.0, 1.0)

    float m0r = -1e30f, m1r = -1e30f;
    float la[4];                          // row-sum accumulator (col0 lanes hold l)
#pragma unroll
    for (int c = 0; c < 4; c++) la[c] = 0.0f;
    float po[16][4];
#pragma unroll
    for (int df = 0; df < 16; df++)
#pragma unroll
        for (int c = 0; c < 4; c++) po[df][c] = 0.0f;

#define FA_ISSUE(KT, STG)                                                          \
    {                                                                              \
        int k0_ = (KT) * 64;                                                       \
        uint32_t* ksd = Ks + (STG) * 64 * KLD2;                                    \
        uint32_t* vsd = Vts + (STG) * 128 * VLD2;                                  \
        _Pragma("unroll")                                                          \
        for (int i = 0; i < 8; i++) {                                              \
            int id = t + 128 * i;                                                  \
            int r = id >> 4, c = id & 15;                                          \
            cpasync16(ksd + r * KLD2 + c * 4, Kb + (size_t)(k0_ + r) * 64 + c * 4);\
        }                                                                          \
        _Pragma("unroll")                                                          \
        for (int i = 0; i < 8; i++) {                                              \
            int id = t + 128 * i;                                                  \
            int r = id >> 3, c = id & 7;                                           \
            cpasync16(vsd + r * VLD2 + c * 4,                                      \
                      Vb + (size_t)r * (TOTAL / 2) + (k0_ >> 1) + c * 4);          \
        }                                                                          \
    }

    int nkt = (PAST + q0 + FBM) / 64;
    FA_ISSUE(0, 0); cpasync_commit();

    for (int kt = 0; kt < nkt; kt++) {
        int k0 = kt * 64;
        bool masked = (k0 >= PAST + q0);
        int rel = k0 - PAST - q0;

        cpasync_wait0();
        __syncthreads();
        if (kt + 1 < nkt) { FA_ISSUE(kt + 1, (kt + 1) & 1); cpasync_commit(); }

        uint32_t kstage = smem_b + (kt & 1) * (64 * KLD2 * 4);
        uint32_t vstage = (kt & 1) * (128 * VLD2 * 4);

        // S = Q K^T : 16 rows x 64 keys (log2-domain scores)
        float sc[8][4];
#pragma unroll
        for (int nf = 0; nf < 8; nf++)
#pragma unroll
            for (int c = 0; c < 4; c++) sc[nf][c] = 0.0f;

#pragma unroll
        for (int q = 0; q < 4; q++) {
#pragma unroll
            for (int nf = 0; nf < 8; nf++) {
                uint32_t b0, b1, b2, b3;
                ldsm4(b0, b1, b2, b3, kstage + koff + nf * (8 * KLD2 * 4) + q * 64);
                mma_f16(sc[nf], qA[q].x, qB[q].x, qA[q].y, qB[q].y, b0, b1);
                mma_f16(sc[nf], qA[q].z, qB[q].z, qA[q].w, qB[q].w, b2, b3);
            }
        }

        if (masked) {
#pragma unroll
            for (int nf = 0; nf < 8; nf++)
#pragma unroll
                for (int c = 0; c < 4; c++) {
                    int col = nf * 8 + 2 * tid4 + (c & 1);
                    int row = mq + gid + 8 * (c >> 1);
                    if (col + rel > row) sc[nf][c] = -1e30f;
                }
        }

        // Warp-private online softmax (rows mq+gid, mq+gid+8), EX2 only
        float rm0 = -1e30f, rm1 = -1e30f;
#pragma unroll
        for (int nf = 0; nf < 8; nf++) {
            rm0 = fmaxf(rm0, fmaxf(sc[nf][0], sc[nf][1]));
            rm1 = fmaxf(rm1, fmaxf(sc[nf][2], sc[nf][3]));
        }
#pragma unroll
        for (int off = 1; off <= 2; off <<= 1) {
            rm0 = fmaxf(rm0, __shfl_xor_sync(0xffffffffu, rm0, off));
            rm1 = fmaxf(rm1, __shfl_xor_sync(0xffffffffu, rm1, off));
        }
        float mn0 = fmaxf(m0r, rm0);
        float mn1 = fmaxf(m1r, rm1);
        float alpha0 = ex2(m0r - mn0);
        float alpha1 = ex2(m1r - mn1);
        m0r = mn0; m1r = mn1;

#pragma unroll
        for (int nf = 0; nf < 8; nf++) {
            sc[nf][0] = ex2(sc[nf][0] - mn0);
            sc[nf][1] = ex2(sc[nf][1] - mn0);
            sc[nf][2] = ex2(sc[nf][2] - mn1);
            sc[nf][3] = ex2(sc[nf][3] - mn1);
        }

        // Rescale O and l accumulators (skip when all alphas exactly 1)
        bool no_rescale = (alpha0 == 1.0f) & (alpha1 == 1.0f);
        if (!__all_sync(0xffffffffu, no_rescale)) {
#pragma unroll
            for (int df = 0; df < 16; df++) {
                po[df][0] *= alpha0; po[df][1] *= alpha0;
                po[df][2] *= alpha1; po[df][3] *= alpha1;
            }
            la[0] *= alpha0; la[1] *= alpha0;
            la[2] *= alpha1; la[3] *= alpha1;
        }

        // O += P V ; l += P * ones  (A from QK output regs, packed half2)
#pragma unroll
        for (int q = 0; q < 2; q++) {
            uint32_t pa[8];
            pa[0] = pack_half2(sc[4 * q + 0][0], sc[4 * q + 0][1]);
            pa[1] = pack_half2(sc[4 * q + 0][2], sc[4 * q + 0][3]);
            pa[2] = pack_half2(sc[4 * q + 1][0], sc[4 * q + 1][1]);
            pa[3] = pack_half2(sc[4 * q + 1][2], sc[4 * q + 1][3]);
            pa[4] = pack_half2(sc[4 * q + 2][0], sc[4 * q + 2][1]);
            pa[5] = pack_half2(sc[4 * q + 2][2], sc[4 * q + 2][3]);
            pa[6] = pack_half2(sc[4 * q + 3][0], sc[4 * q + 3][1]);
            pa[7] = pack_half2(sc[4 * q + 3][2], sc[4 * q + 3][3]);
            // row-sum into la (B = ones)
            mma_f16(la, pa[0], pa[1], pa[2], pa[3], ONE2, ONE2);
            mma_f16(la, pa[4], pa[5], pa[6], pa[7], ONE2, ONE2);
#pragma unroll
            for (int df = 0; df < 16; df++) {
                uint32_t b0, b1, b2, b3;
                ldsm4(b0, b1, b2, b3, smem_b + voff + vstage + df * (8 * VLD2 * 4) + q * 64);
                mma_f16(po[df], pa[0], pa[1], pa[2], pa[3], b0, b1);
                mma_f16(po[df], pa[4], pa[5], pa[6], pa[7], b2, b3);
            }
        }
    }
#undef FA_ISSUE

    // Epilogue: broadcast l from col-0 lanes (tid4==0 of each quad), normalize
    int qbase = lane & ~3;
    float l0 = __shfl_sync(0xffffffffu, la[0], qbase);
    float l1 = __shfl_sync(0xffffffffu, la[2], qbase);
    float inv0 = 1.0f / l0;
    float inv1 = 1.0f / l1;
    int b  = bh >> 4;
    int hd = bh & 15;
    int row0 = q0 + mq + gid;
    int row1 = row0 + 8;
#pragma unroll
    for (int df = 0; df < 16; df++) {
        int cu = hd * 64 + 4 * df + tid4;
        Out[(size_t)(b * SS + row0) * (D_MODEL / 2) + cu] =
            pack_half2(po[df][0] * inv0, po[df][1] * inv0);
        Out[(size_t)(b * SS + row1) * (D_MODEL / 2) + cu] =
            pack_half2(po[df][2] * inv1, po[df][3] * inv1);
    }
}

// ---------------------------------------------------------------------------
extern "C" void kernel_launch(void* const* d_in, const int* in_sizes, int n_in,
                              void* d_out, int out_size) {
    const float* x  = (const float*)d_in[0];
    const float* pk = (const float*)d_in[1];
    const float* pv = (const float*)d_in[2];
    const float* Wq = (const float*)d_in[3];
    const float* Wk = (const float*)d_in[4];
    const float* Wv = (const float*)d_in[5];
    const float* Wo = (const float*)d_in[6];

    float* out = (float*)d_out;
    float* kc  = out + (size_t)BB * SS * D_MODEL;
    float* vc  = kc + (size_t)BHH * TOTAL * DHD;

    uint32_t *gXh, *gWh, *gQh, *gKh, *gVh, *gVtmp, *gAh;
    cudaGetSymbolAddress((void**)&gXh, g_Xh);
    cudaGetSymbolAddress((void**)&gWh, g_Wh);
    cudaGetSymbolAddress((void**)&gQh, g_Qh);
    cudaGetSymbolAddress((void**)&gKh, g_Kh);
    cudaGetSymbolAddress((void**)&gVh, g_Vh);
    cudaGetSymbolAddress((void**)&gVtmp, g_Vtmp);
    cudaGetSymbolAddress((void**)&gAh, g_Ah);

    cudaFuncSetAttribute(gemm_f16_kernel<1>, cudaFuncAttributeMaxDynamicSharedMemorySize, GEMM_SMEM);
    cudaFuncSetAttribute(gemm_f16_kernel<0>, cudaFuncAttributeMaxDynamicSharedMemorySize, GEMM_SMEM);
    cudaFuncSetAttribute(flash_attn_f16_kernel, cudaFuncAttributeMaxDynamicSharedMemorySize, FA_SMEM);

    // [0] all converts in one launch (x + 4 W)
    cvt_all_kernel<<<dim3((M_ROWS * D_MODEL / 4 + 255) / 256, 5), 256>>>(
        (const float4*)x, (const float4*)Wq, (const float4*)Wk,
        (const float4*)Wv, (const float4*)Wo, (uint2*)gXh, (uint2*)gWh);
    // [1] past K
    copy_past_k_kernel<<<(BHH * PAST * DHD / 4 + 255) / 256, 256>>>(
        (const float4*)pk, (float4*)kc, (uint2*)gKh);
    // [2] past V (copy + transpose)
    transpose_past_v_kernel<<<dim3(PAST / 32, DHD / 32, BHH), 256>>>(
        pv, vc, gVh);
    // [3] fused Q/K/V projections
    dim3 qkv_grid(D_MODEL / GBN, M_ROWS / GBM, 3);
    gemm_f16_kernel<1><<<qkv_grid, 512, GEMM_SMEM>>>(
        gXh, gWh, nullptr, kc, vc, gQh, gKh, gVtmp);
    // [4] transpose new V rows
    transpose_v_new_kernel<<<dim3(SS / 32, DHD / 32, BHH), 256>>>(gVtmp, gVh);
    // [5] causal attention  (ncu -s 5 -c 1 profiles THIS launch)
    flash_attn_f16_kernel<<<dim3(SS / FBM, BHH), 128, FA_SMEM>>>(gQh, gKh, gVh, gAh);
    // [6] output projection
    dim3 o_grid(D_MODEL / GBN, M_ROWS / GBM, 1);
    gemm_f16_kernel<0><<<o_grid, 512, GEMM_SMEM>>>(
        gAh, gWh + 3 * (size_t)D_MODEL * D_MODEL / 2, out, nullptr, nullptr,
        nullptr, nullptr, nullptr);
}

// round 17
// speedup vs baseline: 1.0463x; 1.0463x over previous
#include <cuda_runtime.h>
#include <cuda_fp16.h>
#include <cstdint>

#define D_MODEL 2048
#define BB 2
#define SS 2048
#define HH 16
#define DHD 128
#define PAST 2048
#define TOTAL 4096
#define BHH 32
#define M_ROWS 4096
// 1/sqrt(128) * log2(e): scores land in log2 domain -> softmax via EX2 only
#define QK_SCALE_L2E ((float)(0.08838834764831845 * 1.4426950408889634))

// Scratch (allocation-free rule). All hold packed fp16 (2 per uint32).
__device__ uint32_t g_Xh[(size_t)M_ROWS * D_MODEL / 2];
__device__ uint32_t g_Wh[4 * (size_t)D_MODEL * D_MODEL / 2];
__device__ uint32_t g_Qh[(size_t)BHH * SS * DHD / 2];    // PERMUTED fragment layout, pre-scaled
__device__ uint32_t g_Kh[(size_t)BHH * TOTAL * DHD / 2]; // plain (bh,key,dh)
__device__ uint32_t g_Vh[(size_t)BHH * DHD * TOTAL / 2]; // V transposed (bh,dh,key), plain
__device__ uint32_t g_Vtmp[(size_t)BHH * SS * DHD / 2];  // new-V plain (bh,s,dh) staging
__device__ uint32_t g_Ah[(size_t)BB * SS * D_MODEL / 2]; // attn (b,s,dm), plain

// ---------------------------------------------------------------------------
// Helpers
// ---------------------------------------------------------------------------
__device__ __forceinline__ uint32_t pack_half2(float lo, float hi) {
    uint32_t r;
    asm("cvt.rn.f16x2.f32 %0, %1, %2;" : "=r"(r) : "f"(hi), "f"(lo));
    return r;
}

__device__ __forceinline__ void mma_f16(float* c,
                                        uint32_t a0, uint32_t a1, uint32_t a2, uint32_t a3,
                                        uint32_t b0, uint32_t b1) {
    asm volatile(
        "mma.sync.aligned.m16n8k16.row.col.f32.f16.f16.f32 "
        "{%0,%1,%2,%3}, {%4,%5,%6,%7}, {%8,%9}, {%0,%1,%2,%3};"
        : "+f"(c[0]), "+f"(c[1]), "+f"(c[2]), "+f"(c[3])
        : "r"(a0), "r"(a1), "r"(a2), "r"(a3), "r"(b0), "r"(b1));
}

__device__ __forceinline__ void ldsm4(uint32_t& r0, uint32_t& r1, uint32_t& r2, uint32_t& r3,
                                      uint32_t saddr) {
    asm volatile("ldmatrix.sync.aligned.m8n8.x4.shared.b16 {%0,%1,%2,%3}, [%4];"
                 : "=r"(r0), "=r"(r1), "=r"(r2), "=r"(r3) : "r"(saddr));
}
__device__ __forceinline__ void ldsm2(uint32_t& r0, uint32_t& r1, uint32_t saddr) {
    asm volatile("ldmatrix.sync.aligned.m8n8.x2.shared.b16 {%0,%1}, [%2];"
                 : "=r"(r0), "=r"(r1) : "r"(saddr));
}

// exp2 on MUFU: 1 issue slot. ex2(0) == 1.0f exactly.
__device__ __forceinline__ float ex2(float x) {
    float r;
    asm("ex2.approx.ftz.f32 %0, %1;" : "=f"(r) : "f"(x));
    return r;
}

__device__ __forceinline__ void cpasync16(void* smem_dst, const void* gsrc) {
    uint32_t s = (uint32_t)__cvta_generic_to_shared(smem_dst);
    asm volatile("cp.async.cg.shared.global [%0], [%1], 16;" :: "r"(s), "l"(gsrc));
}
__device__ __forceinline__ void cpasync_commit() {
    asm volatile("cp.async.commit_group;");
}
__device__ __forceinline__ void cpasync_wait0() {
    asm volatile("cp.async.wait_group 0;");
}
__device__ __forceinline__ void cpasync_wait2() {
    asm volatile("cp.async.wait_group 2;");
}

// ---------------------------------------------------------------------------
// Prep kernels. cvt_all merges x + 4 W converts into ONE launch.
// ---------------------------------------------------------------------------
__global__ void cvt_all_kernel(const float4* __restrict__ x,
                               const float4* __restrict__ w0, const float4* __restrict__ w1,
                               const float4* __restrict__ w2, const float4* __restrict__ w3,
                               uint2* __restrict__ xh, uint2* __restrict__ wh) {
    int z = blockIdx.y;
    const int n4w = D_MODEL * D_MODEL / 4;
    const int n4x = M_ROWS * D_MODEL / 4;
    int i = blockIdx.x * blockDim.x + threadIdx.x;
    if (z < 4) {
        if (i >= n4w) return;
        const float4* src = (z == 0) ? w0 : (z == 1) ? w1 : (z == 2) ? w2 : w3;
        float4 v = src[i];
        wh[(size_t)z * n4w + i] = make_uint2(pack_half2(v.x, v.y), pack_half2(v.z, v.w));
    } else {
        if (i >= n4x) return;
        float4 v = x[i];
        xh[i] = make_uint2(pack_half2(v.x, v.y), pack_half2(v.z, v.w));
    }
}

__global__ void copy_past_k_kernel(const float4* __restrict__ pk,
                                   float4* __restrict__ kc, uint2* __restrict__ kh) {
    int i = blockIdx.x * blockDim.x + threadIdx.x;
    if (i >= BHH * PAST * DHD / 4) return;
    int bh  = i >> 16;
    int rem = i & 65535;
    int dst = (bh << 17) + rem;
    float4 v = pk[i];
    kc[dst] = v;
    kh[dst] = make_uint2(pack_half2(v.x, v.y), pack_half2(v.z, v.w));
}

__global__ __launch_bounds__(256) void transpose_past_v_kernel(
    const float* __restrict__ pv, float* __restrict__ vc, uint32_t* __restrict__ vt) {
    __shared__ float ts[32][33];
    int bh = blockIdx.z;
    int k0 = blockIdx.x * 32;
    int d0 = blockIdx.y * 32;
    int tx = threadIdx.x & 31, ty = threadIdx.x >> 5;

    const float* src = pv + ((size_t)bh * PAST + k0) * DHD + d0;
    float* cdst      = vc + ((size_t)bh * TOTAL + k0) * DHD + d0;
#pragma unroll
    for (int j = 0; j < 4; j++) {
        int r = ty + 8 * j;
        float v = src[(size_t)r * DHD + tx];
        cdst[(size_t)r * DHD + tx] = v;
        ts[r][tx] = v;
    }
    __syncthreads();
    uint32_t* td = vt + (size_t)bh * DHD * (TOTAL / 2);
    if (tx < 16) {
#pragma unroll
        for (int j = 0; j < 4; j++) {
            int dd = ty + 8 * j;
            td[(size_t)(d0 + dd) * (TOTAL / 2) + (k0 >> 1) + tx] =
                pack_half2(ts[2 * tx][dd], ts[2 * tx + 1][dd]);
        }
    }
}

__global__ __launch_bounds__(256) void transpose_v_new_kernel(
    const uint32_t* __restrict__ vtmp, uint32_t* __restrict__ vt) {
    __shared__ unsigned short ts[32][34];
    int bh = blockIdx.z;
    int k0 = blockIdx.x * 32;
    int d0 = blockIdx.y * 32;
    int t  = threadIdx.x;
    {
        int r = t >> 3, cb = t & 7;
#pragma unroll
        for (int i = 0; i < 2; i++) {
            int c = cb + 8 * i;
            uint32_t v = vtmp[((size_t)bh * SS + k0 + r) * 64 + (d0 >> 1) + c];
            ts[r][2 * c]     = (unsigned short)(v & 0xffffu);
            ts[r][2 * c + 1] = (unsigned short)(v >> 16);
        }
    }
    __syncthreads();
    {
        int dd = t >> 3, kb = t & 7;
        uint32_t* td = vt + (size_t)bh * DHD * (TOTAL / 2);
#pragma unroll
        for (int i = 0; i < 2; i++) {
            int kp = kb + 8 * i;
            uint32_t lo = ts[2 * kp][dd];
            uint32_t hi = ts[2 * kp + 1][dd];
            td[(size_t)(d0 + dd) * (TOTAL / 2) + ((PAST + k0) >> 1) + kp] = lo | (hi << 16);
        }
    }
}

// ---------------------------------------------------------------------------
// FP16 GEMM, retiled for occupancy: CTA 128x128, 256 threads, 8 warps
// (2m x 4n of the proven 64x32 warp tile), BK=32, 4-stage cp.async.
// regs ~92 x 256 = 23.5K -> 2 CTAs/SM by RF; smem 80KB x2 = 160KB.
// Two independent barrier domains per SM interleave load/compute phases.
// ---------------------------------------------------------------------------
#define GBM 128
#define GBN 128
#define LDWA 20
#define GSTG ((GBM + GBN) * LDWA)        // 5120 u32 per stage
#define GEMM_SMEM (4 * GSTG * 4)         // 81920 B

template <int FUSED>
__global__ __launch_bounds__(256) void gemm_f16_kernel(
    const uint32_t* __restrict__ A, const uint32_t* __restrict__ Wt,
    float* __restrict__ C0, float* __restrict__ C1, float* __restrict__ C2,
    uint32_t* __restrict__ Qh, uint32_t* __restrict__ Kh, uint32_t* __restrict__ Vt) {
    extern __shared__ uint32_t smg[];
    const int PITCH = D_MODEL / 2;

    int t    = threadIdx.x;
    int warp = t >> 5, lane = t & 31;
    int gid  = lane >> 2, tid4 = lane & 3;
    int wm   = (warp & 1) * 64;
    int wn   = (warp >> 1) * 32;
    int m0   = blockIdx.y * GBM;
    int n0   = blockIdx.x * GBN;
    int z    = FUSED ? blockIdx.z : 0;

    const uint32_t* Ab = A + (size_t)m0 * PITCH;
    const uint32_t* Bb = Wt + (FUSED ? (size_t)z * D_MODEL * PITCH : 0) + (size_t)n0 * PITCH;

    float acc[4][4][4];
#pragma unroll
    for (int mf = 0; mf < 4; mf++)
#pragma unroll
        for (int nf = 0; nf < 4; nf++)
#pragma unroll
            for (int c = 0; c < 4; c++) acc[mf][nf][c] = 0.0f;

    uint32_t smem_b = (uint32_t)__cvta_generic_to_shared(smg);
    uint32_t aoff = ((wm + (lane & 15)) * LDWA + (lane >> 4) * 4) * 4;
    uint32_t boff = (GBM * LDWA + (wn + (lane & 7)) * LDWA + ((lane >> 3) & 1) * 4) * 4;

    const int NT = D_MODEL / 32;   // 64

#define GISSUE(KT, STG)                                                         \
    {                                                                           \
        uint32_t* As_ = smg + (STG) * GSTG;                                     \
        uint32_t* Bs_ = As_ + GBM * LDWA;                                       \
        const uint32_t* ab = Ab + (KT) * 16;                                    \
        const uint32_t* bb = Bb + (KT) * 16;                                    \
        _Pragma("unroll")                                                       \
        for (int j = 0; j < 2; j++) {                                           \
            int g = t + 256 * j;                                                \
            int r = g >> 2, c = g & 3;                                          \
            cpasync16(As_ + r * LDWA + c * 4, ab + (size_t)r * PITCH + c * 4);  \
            cpasync16(Bs_ + r * LDWA + c * 4, bb + (size_t)r * PITCH + c * 4);  \
        }                                                                       \
    }

    GISSUE(0, 0); cpasync_commit();
    GISSUE(1, 1); cpasync_commit();
    GISSUE(2, 2); cpasync_commit();

    for (int kt = 0; kt < NT; kt++) {
        cpasync_wait2();       // chunk kt landed (<=2 younger outstanding)
        __syncthreads();       // visible; all warps past reads of buffer (kt+3)&3
        if (kt + 3 < NT) {
            GISSUE(kt + 3, (kt + 3) & 3);
            cpasync_commit();
        }

        uint32_t sb = smem_b + (kt & 3) * (GSTG * 4);
        uint32_t bf[4][4];
#pragma unroll
        for (int nf = 0; nf < 4; nf++) {
            ldsm2(bf[nf][0], bf[nf][1], sb + boff + nf * (8 * LDWA * 4));
            ldsm2(bf[nf][2], bf[nf][3], sb + boff + nf * (8 * LDWA * 4) + 32);
        }
#pragma unroll
        for (int mf = 0; mf < 4; mf++) {
            uint32_t x0, x1, x2, x3, y0, y1, y2, y3;
            ldsm4(x0, x1, x2, x3, sb + aoff + mf * (16 * LDWA * 4));
            ldsm4(y0, y1, y2, y3, sb + aoff + mf * (16 * LDWA * 4) + 32);
#pragma unroll
            for (int nf = 0; nf < 4; nf++) {
                mma_f16(acc[mf][nf], x0, x1, x2, x3, bf[nf][0], bf[nf][1]);
                mma_f16(acc[mf][nf], y0, y1, y2, y3, bf[nf][2], bf[nf][3]);
            }
        }
    }
#undef GISSUE

    // Epilogue
    if (FUSED && z == 0) {
        int nbase = n0 + wn;
        int hd  = nbase >> 7;
        int blk = (nbase & 127) >> 5;
#pragma unroll
        for (int mf = 0; mf < 4; mf++)
#pragma unroll
            for (int h = 0; h < 2; h++) {
                int m = m0 + wm + 16 * mf + gid + 8 * h;
                int bb = m >> 11, ss = m & 2047;
                int bhh = bb * HH + hd;
                uint4 u;
                u.x = pack_half2(acc[mf][0][2 * h] * QK_SCALE_L2E, acc[mf][0][2 * h + 1] * QK_SCALE_L2E);
                u.y = pack_half2(acc[mf][1][2 * h] * QK_SCALE_L2E, acc[mf][1][2 * h + 1] * QK_SCALE_L2E);
                u.z = pack_half2(acc[mf][2][2 * h] * QK_SCALE_L2E, acc[mf][2][2 * h + 1] * QK_SCALE_L2E);
                u.w = pack_half2(acc[mf][3][2 * h] * QK_SCALE_L2E, acc[mf][3][2 * h + 1] * QK_SCALE_L2E);
                *(uint4*)&Qh[((size_t)bhh * SS + ss) * 64 + blk * 16 + 4 * tid4] = u;
            }
    } else {
#pragma unroll
        for (int mf = 0; mf < 4; mf++)
#pragma unroll
            for (int nf = 0; nf < 4; nf++)
#pragma unroll
                for (int h = 0; h < 2; h++) {
                    int m = m0 + wm + 16 * mf + gid + 8 * h;
                    int n = n0 + wn + 8 * nf + 2 * tid4;
                    float vx = acc[mf][nf][2 * h];
                    float vy = acc[mf][nf][2 * h + 1];
                    if (!FUSED) {
                        *(float2*)&C0[(size_t)m * D_MODEL + n] = make_float2(vx, vy);
                    } else {
                        int bb = m >> 11, ss = m & 2047;
                        int hd = n >> 7,  di = n & 127;
                        int bhh = bb * HH + hd;
                        if (z == 1) {
                            size_t rowk = (size_t)bhh * TOTAL + (PAST + ss);
                            *(float2*)&C1[rowk * DHD + di] = make_float2(vx, vy);
                            Kh[rowk * 64 + (di >> 1)] = pack_half2(vx, vy);
                        } else {
                            size_t rowk = (size_t)bhh * TOTAL + (PAST + ss);
                            *(float2*)&C2[rowk * DHD + di] = make_float2(vx, vy);
                            Vt[((size_t)bhh * SS + ss) * 64 + (di >> 1)] = pack_half2(vx, vy);
                        }
                    }
                }
    }
}

// ---------------------------------------------------------------------------
// Flash attention, fp16 m16n8k16 mma (round-16 version: ones-column row sum).
// ---------------------------------------------------------------------------
#define FBM 64
#define KLD2 68
#define VLD2 36
#define FA_SMEM ((2 * 64 * KLD2 + 2 * 128 * VLD2) * 4)   // 71680 B

__global__ __launch_bounds__(128, 2) void flash_attn_f16_kernel(
    const uint32_t* __restrict__ Qh, const uint32_t* __restrict__ Khg,
    const uint32_t* __restrict__ Vhg, uint32_t* __restrict__ Out) {
    extern __shared__ uint32_t sm[];
    uint32_t* Ks  = sm;                   // [2][64][KLD2]
    uint32_t* Vts = sm + 2 * 64 * KLD2;   // [2][128][VLD2]

    int t    = threadIdx.x;
    int warp = t >> 5, lane = t & 31;
    int gid  = lane >> 2, tid4 = lane & 3;
    int mq   = warp * 16;

    int bh = blockIdx.y;
    int q0 = (gridDim.x - 1 - blockIdx.x) * FBM;

    const uint32_t* Kb = Khg + (size_t)bh * TOTAL * 64;
    const uint32_t* Vb = Vhg + (size_t)bh * DHD * (TOTAL / 2);

    uint4 qA[4], qB[4];
    {
        const uint32_t* Qr0 = Qh + ((size_t)bh * SS + (q0 + mq + gid)) * 64 + 4 * tid4;
        const uint32_t* Qr1 = Qr0 + 8 * 64;
#pragma unroll
        for (int blk = 0; blk < 4; blk++) {
            qA[blk] = *(const uint4*)&Qr0[blk * 16];
            qB[blk] = *(const uint4*)&Qr1[blk * 16];
        }
    }

    uint32_t smem_b = (uint32_t)__cvta_generic_to_shared(sm);
    uint32_t koff = ((lane & 7) * KLD2 + (lane >> 3) * 4) * 4;
    uint32_t voff = (2 * 64 * KLD2) * 4 + ((lane & 7) * VLD2 + (lane >> 3) * 4) * 4;

    const uint32_t ONE2 = 0x3C003C00u;

    float m0r = -1e30f, m1r = -1e30f;
    float la[4];
#pragma unroll
    for (int c = 0; c < 4; c++) la[c] = 0.0f;
    float po[16][4];
#pragma unroll
    for (int df = 0; df < 16; df++)
#pragma unroll
        for (int c = 0; c < 4; c++) po[df][c] = 0.0f;

#define FA_ISSUE(KT, STG)                                                          \
    {                                                                              \
        int k0_ = (KT) * 64;                                                       \
        uint32_t* ksd = Ks + (STG) * 64 * KLD2;                                    \
        uint32_t* vsd = Vts + (STG) * 128 * VLD2;                                  \
        _Pragma("unroll")                                                          \
        for (int i = 0; i < 8; i++) {                                              \
            int id = t + 128 * i;                                                  \
            int r = id >> 4, c = id & 15;                                          \
            cpasync16(ksd + r * KLD2 + c * 4, Kb + (size_t)(k0_ + r) * 64 + c * 4);\
        }                                                                          \
        _Pragma("unroll")                                                          \
        for (int i = 0; i < 8; i++) {                                              \
            int id = t + 128 * i;                                                  \
            int r = id >> 3, c = id & 7;                                           \
            cpasync16(vsd + r * VLD2 + c * 4,                                      \
                      Vb + (size_t)r * (TOTAL / 2) + (k0_ >> 1) + c * 4);          \
        }                                                                          \
    }

    int nkt = (PAST + q0 + FBM) / 64;
    FA_ISSUE(0, 0); cpasync_commit();

    for (int kt = 0; kt < nkt; kt++) {
        int k0 = kt * 64;
        bool masked = (k0 >= PAST + q0);
        int rel = k0 - PAST - q0;

        cpasync_wait0();
        __syncthreads();
        if (kt + 1 < nkt) { FA_ISSUE(kt + 1, (kt + 1) & 1); cpasync_commit(); }

        uint32_t kstage = smem_b + (kt & 1) * (64 * KLD2 * 4);
        uint32_t vstage = (kt & 1) * (128 * VLD2 * 4);

        float sc[8][4];
#pragma unroll
        for (int nf = 0; nf < 8; nf++)
#pragma unroll
            for (int c = 0; c < 4; c++) sc[nf][c] = 0.0f;

#pragma unroll
        for (int q = 0; q < 4; q++) {
#pragma unroll
            for (int nf = 0; nf < 8; nf++) {
                uint32_t b0, b1, b2, b3;
                ldsm4(b0, b1, b2, b3, kstage + koff + nf * (8 * KLD2 * 4) + q * 64);
                mma_f16(sc[nf], qA[q].x, qB[q].x, qA[q].y, qB[q].y, b0, b1);
                mma_f16(sc[nf], qA[q].z, qB[q].z, qA[q].w, qB[q].w, b2, b3);
            }
        }

        if (masked) {
#pragma unroll
            for (int nf = 0; nf < 8; nf++)
#pragma unroll
                for (int c = 0; c < 4; c++) {
                    int col = nf * 8 + 2 * tid4 + (c & 1);
                    int row = mq + gid + 8 * (c >> 1);
                    if (col + rel > row) sc[nf][c] = -1e30f;
                }
        }

        float rm0 = -1e30f, rm1 = -1e30f;
#pragma unroll
        for (int nf = 0; nf < 8; nf++) {
            rm0 = fmaxf(rm0, fmaxf(sc[nf][0], sc[nf][1]));
            rm1 = fmaxf(rm1, fmaxf(sc[nf][2], sc[nf][3]));
        }
#pragma unroll
        for (int off = 1; off <= 2; off <<= 1) {
            rm0 = fmaxf(rm0, __shfl_xor_sync(0xffffffffu, rm0, off));
            rm1 = fmaxf(rm1, __shfl_xor_sync(0xffffffffu, rm1, off));
        }
        float mn0 = fmaxf(m0r, rm0);
        float mn1 = fmaxf(m1r, rm1);
        float alpha0 = ex2(m0r - mn0);
        float alpha1 = ex2(m1r - mn1);
        m0r = mn0; m1r = mn1;

#pragma unroll
        for (int nf = 0; nf < 8; nf++) {
            sc[nf][0] = ex2(sc[nf][0] - mn0);
            sc[nf][1] = ex2(sc[nf][1] - mn0);
            sc[nf][2] = ex2(sc[nf][2] - mn1);
            sc[nf][3] = ex2(sc[nf][3] - mn1);
        }

        bool no_rescale = (alpha0 == 1.0f) & (alpha1 == 1.0f);
        if (!__all_sync(0xffffffffu, no_rescale)) {
#pragma unroll
            for (int df = 0; df < 16; df++) {
                po[df][0] *= alpha0; po[df][1] *= alpha0;
                po[df][2] *= alpha1; po[df][3] *= alpha1;
            }
            la[0] *= alpha0; la[1] *= alpha0;
            la[2] *= alpha1; la[3] *= alpha1;
        }

#pragma unroll
        for (int q = 0; q < 2; q++) {
            uint32_t pa[8];
            pa[0] = pack_half2(sc[4 * q + 0][0], sc[4 * q + 0][1]);
            pa[1] = pack_half2(sc[4 * q + 0][2], sc[4 * q + 0][3]);
            pa[2] = pack_half2(sc[4 * q + 1][0], sc[4 * q + 1][1]);
            pa[3] = pack_half2(sc[4 * q + 1][2], sc[4 * q + 1][3]);
            pa[4] = pack_half2(sc[4 * q + 2][0], sc[4 * q + 2][1]);
            pa[5] = pack_half2(sc[4 * q + 2][2], sc[4 * q + 2][3]);
            pa[6] = pack_half2(sc[4 * q + 3][0], sc[4 * q + 3][1]);
            pa[7] = pack_half2(sc[4 * q + 3][2], sc[4 * q + 3][3]);
            mma_f16(la, pa[0], pa[1], pa[2], pa[3], ONE2, ONE2);
            mma_f16(la, pa[4], pa[5], pa[6], pa[7], ONE2, ONE2);
#pragma unroll
            for (int df = 0; df < 16; df++) {
                uint32_t b0, b1, b2, b3;
                ldsm4(b0, b1, b2, b3, smem_b + voff + vstage + df * (8 * VLD2 * 4) + q * 64);
                mma_f16(po[df], pa[0], pa[1], pa[2], pa[3], b0, b1);
                mma_f16(po[df], pa[4], pa[5], pa[6], pa[7], b2, b3);
            }
        }
    }
#undef FA_ISSUE

    int qbase = lane & ~3;
    float l0 = __shfl_sync(0xffffffffu, la[0], qbase);
    float l1 = __shfl_sync(0xffffffffu, la[2], qbase);
    float inv0 = 1.0f / l0;
    float inv1 = 1.0f / l1;
    int b  = bh >> 4;
    int hd = bh & 15;
    int row0 = q0 + mq + gid;
    int row1 = row0 + 8;
#pragma unroll
    for (int df = 0; df < 16; df++) {
        int cu = hd * 64 + 4 * df + tid4;
        Out[(size_t)(b * SS + row0) * (D_MODEL / 2) + cu] =
            pack_half2(po[df][0] * inv0, po[df][1] * inv0);
        Out[(size_t)(b * SS + row1) * (D_MODEL / 2) + cu] =
            pack_half2(po[df][2] * inv1, po[df][3] * inv1);
    }
}

// ---------------------------------------------------------------------------
extern "C" void kernel_launch(void* const* d_in, const int* in_sizes, int n_in,
                              void* d_out, int out_size) {
    const float* x  = (const float*)d_in[0];
    const float* pk = (const float*)d_in[1];
    const float* pv = (const float*)d_in[2];
    const float* Wq = (const float*)d_in[3];
    const float* Wk = (const float*)d_in[4];
    const float* Wv = (const float*)d_in[5];
    const float* Wo = (const float*)d_in[6];

    float* out = (float*)d_out;
    float* kc  = out + (size_t)BB * SS * D_MODEL;
    float* vc  = kc + (size_t)BHH * TOTAL * DHD;

    uint32_t *gXh, *gWh, *gQh, *gKh, *gVh, *gVtmp, *gAh;
    cudaGetSymbolAddress((void**)&gXh, g_Xh);
    cudaGetSymbolAddress((void**)&gWh, g_Wh);
    cudaGetSymbolAddress((void**)&gQh, g_Qh);
    cudaGetSymbolAddress((void**)&gKh, g_Kh);
    cudaGetSymbolAddress((void**)&gVh, g_Vh);
    cudaGetSymbolAddress((void**)&gVtmp, g_Vtmp);
    cudaGetSymbolAddress((void**)&gAh, g_Ah);

    cudaFuncSetAttribute(gemm_f16_kernel<1>, cudaFuncAttributeMaxDynamicSharedMemorySize, GEMM_SMEM);
    cudaFuncSetAttribute(gemm_f16_kernel<0>, cudaFuncAttributeMaxDynamicSharedMemorySize, GEMM_SMEM);
    cudaFuncSetAttribute(flash_attn_f16_kernel, cudaFuncAttributeMaxDynamicSharedMemorySize, FA_SMEM);

    // [0] all converts in one launch (x + 4 W)
    cvt_all_kernel<<<dim3((M_ROWS * D_MODEL / 4 + 255) / 256, 5), 256>>>(
        (const float4*)x, (const float4*)Wq, (const float4*)Wk,
        (const float4*)Wv, (const float4*)Wo, (uint2*)gXh, (uint2*)gWh);
    // [1] past K
    copy_past_k_kernel<<<(BHH * PAST * DHD / 4 + 255) / 256, 256>>>(
        (const float4*)pk, (float4*)kc, (uint2*)gKh);
    // [2] past V (copy + transpose)
    transpose_past_v_kernel<<<dim3(PAST / 32, DHD / 32, BHH), 256>>>(
        pv, vc, gVh);
    // [3] fused Q/K/V projections (128x128 CTAs, 2/SM)
    dim3 qkv_grid(D_MODEL / GBN, M_ROWS / GBM, 3);  // (16, 32, 3)
    gemm_f16_kernel<1><<<qkv_grid, 256, GEMM_SMEM>>>(
        gXh, gWh, nullptr, kc, vc, gQh, gKh, gVtmp);
    // [4] transpose new V rows
    transpose_v_new_kernel<<<dim3(SS / 32, DHD / 32, BHH), 256>>>(gVtmp, gVh);
    // [5] causal attention
    flash_attn_f16_kernel<<<dim3(SS / FBM, BHH), 128, FA_SMEM>>>(gQh, gKh, gVh, gAh);
    // [6] output projection
    dim3 o_grid(D_MODEL / GBN, M_ROWS / GBM, 1);
    gemm_f16_kernel<0><<<o_grid, 256, GEMM_SMEM>>>(
        gAh, gWh + 3 * (size_t)D_MODEL * D_MODEL / 2, out, nullptr, nullptr,
        nullptr, nullptr, nullptr);
}